// round 16
// baseline (speedup 1.0000x reference)
#include <cuda_runtime.h>
#include <cuda_bf16.h>

// AffineAugment: per-batch rigid affine warp [B,H,W,D,1] fp32, trilinear, zero fill.
// B=4, H=W=D=192.
// One thread = FOUR output voxels (i, j + q*48, k). Round 14 showed ptxas
// serialized the four gathers at 32 regs; this version fuses the four interior
// fast paths into ONE straight-line block: all 32 immediate-offset LDGs issued
// before any lerp math -> true per-thread MLP ~32 (latency-bound kernel).
// Border/invalid warps take the per-sample fallback path.

#define BB  4
#define HH  192
#define WW  192
#define DD  192
#define JQ  (WW / 4)      // 48
#define SX  (WW * DD)     // +x stride

__constant__ float c_mats[BB * 12];

// general per-sample path (bounds + clamped offsets); used off the fast path
__device__ __forceinline__ float sample_one(const float* __restrict__ vb,
                                            float lx, float ly, float lz)
{
    const float lo = fminf(fminf(lx, ly), lz);
    const float hi = fmaxf(fmaxf(lx, ly), lz);
    if (!((lo >= 0.0f) & (hi <= (float)(HH - 1)))) return 0.0f;

    const int ix0 = __float2int_rd(lx);
    const int iy0 = __float2int_rd(ly);
    const int iz0 = __float2int_rd(lz);
    const float tx = lx - (float)ix0;
    const float ty = ly - (float)iy0;
    const float tz = lz - (float)iz0;

    const int ox = (ix0 < HH - 1) ? SX : 0;
    const int oy = (iy0 < WW - 1) ? DD : 0;
    const int oz = (iz0 < DD - 1) ? 1  : 0;

    const float* __restrict__ p0 = vb + (ix0 * WW + iy0) * DD + iz0;
    const float c000 = __ldg(p0);
    const float c001 = __ldg(p0 + oz);
    const float c010 = __ldg(p0 + oy);
    const float c011 = __ldg(p0 + oy + oz);
    const float c100 = __ldg(p0 + ox);
    const float c101 = __ldg(p0 + ox + oz);
    const float c110 = __ldg(p0 + ox + oy);
    const float c111 = __ldg(p0 + ox + oy + oz);

    const float c00 = fmaf(tz, c001 - c000, c000);
    const float c01 = fmaf(tz, c011 - c010, c010);
    const float c10 = fmaf(tz, c101 - c100, c100);
    const float c11 = fmaf(tz, c111 - c110, c110);
    const float c0  = fmaf(ty, c01 - c00, c00);
    const float c1  = fmaf(ty, c11 - c10, c10);
    return fmaf(tx, c1 - c0, c0);
}

__global__ void __launch_bounds__(192)
affine_warp_kernel(const float* __restrict__ x,
                   float* __restrict__ out)
{
    const int k = threadIdx.x;
    const int j = blockIdx.x;          // 0..47 ; voxels at j + q*48
    const int i = blockIdx.y;
    const int b = blockIdx.z;

    const float* M = c_mats + b * 12;
    const float fi = (float)i, fj = (float)j, fk = (float)k;
    const float dxj = M[1] * (float)JQ;
    const float dyj = M[5] * (float)JQ;
    const float dzj = M[9] * (float)JQ;

    float lx[4], ly[4], lz[4];
    lx[0] = fmaf(M[0], fi, fmaf(M[1], fj, fmaf(M[ 2], fk, M[ 3])));
    ly[0] = fmaf(M[4], fi, fmaf(M[5], fj, fmaf(M[ 6], fk, M[ 7])));
    lz[0] = fmaf(M[8], fi, fmaf(M[9], fj, fmaf(M[10], fk, M[11])));
#pragma unroll
    for (int q = 1; q < 4; q++) {
        lx[q] = lx[q-1] + dxj;
        ly[q] = ly[q-1] + dyj;
        lz[q] = lz[q-1] + dzj;
    }

    // combined window over all four sample locations
    float lo_all = lx[0], hi_all = lx[0];
#pragma unroll
    for (int q = 0; q < 4; q++) {
        lo_all = fminf(lo_all, fminf(fminf(lx[q], ly[q]), lz[q]));
        hi_all = fmaxf(hi_all, fmaxf(fmaxf(lx[q], ly[q]), lz[q]));
    }

    const float* __restrict__ vb = x + (size_t)b * (HH * WW * DD);

    float v[4];
    if ((lo_all >= 0.0f) & (hi_all < (float)(HH - 1))) {
        // ---- fast path: all 4 samples strictly interior ----
        const float* p[4];
        float tx[4], ty[4], tz[4];
#pragma unroll
        for (int q = 0; q < 4; q++) {
            const int ix0 = __float2int_rd(lx[q]);
            const int iy0 = __float2int_rd(ly[q]);
            const int iz0 = __float2int_rd(lz[q]);
            tx[q] = lx[q] - (float)ix0;
            ty[q] = ly[q] - (float)iy0;
            tz[q] = lz[q] - (float)iz0;
            p[q] = vb + (ix0 * WW + iy0) * DD + iz0;
        }

        // phase 1: issue ALL 32 loads (immediate offsets, no consumption yet)
        float c[4][8];
#pragma unroll
        for (int q = 0; q < 4; q++) {
            c[q][0] = __ldg(p[q]);
            c[q][1] = __ldg(p[q] + 1);
            c[q][2] = __ldg(p[q] + DD);
            c[q][3] = __ldg(p[q] + DD + 1);
            c[q][4] = __ldg(p[q] + SX);
            c[q][5] = __ldg(p[q] + SX + 1);
            c[q][6] = __ldg(p[q] + SX + DD);
            c[q][7] = __ldg(p[q] + SX + DD + 1);
        }

        // phase 2: lerp
#pragma unroll
        for (int q = 0; q < 4; q++) {
            const float c00 = fmaf(tz[q], c[q][1] - c[q][0], c[q][0]);
            const float c01 = fmaf(tz[q], c[q][3] - c[q][2], c[q][2]);
            const float c10 = fmaf(tz[q], c[q][5] - c[q][4], c[q][4]);
            const float c11 = fmaf(tz[q], c[q][7] - c[q][6], c[q][6]);
            const float c0  = fmaf(ty[q], c01 - c00, c00);
            const float c1  = fmaf(ty[q], c11 - c10, c10);
            v[q] = fmaf(tx[q], c1 - c0, c0);
        }
    } else {
        // ---- fallback: border / invalid (warp-coherent slivers) ----
#pragma unroll
        for (int q = 0; q < 4; q++)
            v[q] = sample_one(vb, lx[q], ly[q], lz[q]);
    }

    float* __restrict__ o = out + ((size_t)((b * HH + i) * WW + j) * DD + k);
    const size_t step = (size_t)JQ * DD;
    __stcs(o,            v[0]);
    __stcs(o + step,     v[1]);
    __stcs(o + 2 * step, v[2]);
    __stcs(o + 3 * step, v[3]);
}

extern "C" void kernel_launch(void* const* d_in, const int* in_sizes, int n_in,
                              void* d_out, int out_size)
{
    const float* x    = (const float*)d_in[0];
    const float* mats = (const float*)d_in[1];
    float* out        = (float*)d_out;

    cudaMemcpyToSymbolAsync(c_mats, mats, BB * 12 * sizeof(float), 0,
                            cudaMemcpyDeviceToDevice);

    dim3 grid(JQ, HH, BB);     // (j quarter, i, b)
    dim3 block(DD);            // k
    affine_warp_kernel<<<grid, block>>>(x, out);
}

// round 17
// speedup vs baseline: 1.0464x; 1.0464x over previous
#include <cuda_runtime.h>
#include <cuda_bf16.h>

// AffineAugment: per-batch rigid affine warp [B,H,W,D,1] fp32, trilinear, zero fill.
// B=4, H=W=D=192.
// Round-14 structure (best kernel: 92.5us): one thread = FOUR output voxels
// (i, j + q*48, k); warp spans 32 consecutive z per tap (minimal L1 lines);
// interior fast path with immediate-offset taps; warp-coherent border fallback.
// NEW vs R14: mats broadcast through SMEM (12 LDG per block + LDS) instead of
// __constant__ + cudaMemcpyToSymbolAsync -> deletes the ~5.8us graph-node tax.

#define BB  4
#define HH  192
#define WW  192
#define DD  192
#define JQ  (WW / 4)      // 48
#define SX  (WW * DD)     // +x stride

// one 8-tap trilinear sample; fast path when hi<191 (all offsets immediate)
__device__ __forceinline__ float sample_one(const float* __restrict__ vb,
                                            float lx, float ly, float lz)
{
    const float lo = fminf(fminf(lx, ly), lz);
    const float hi = fmaxf(fmaxf(lx, ly), lz);
    if (!((lo >= 0.0f) & (hi <= (float)(HH - 1)))) return 0.0f;

    const int ix0 = __float2int_rd(lx);
    const int iy0 = __float2int_rd(ly);
    const int iz0 = __float2int_rd(lz);
    const float tx = lx - (float)ix0;
    const float ty = ly - (float)iy0;
    const float tz = lz - (float)iz0;

    const float* __restrict__ p0 = vb + (ix0 * WW + iy0) * DD + iz0;

    float c000, c001, c010, c011, c100, c101, c110, c111;
    if (hi < (float)(HH - 1)) {
        c000 = __ldg(p0);
        c001 = __ldg(p0 + 1);
        c010 = __ldg(p0 + DD);
        c011 = __ldg(p0 + DD + 1);
        c100 = __ldg(p0 + SX);
        c101 = __ldg(p0 + SX + 1);
        c110 = __ldg(p0 + SX + DD);
        c111 = __ldg(p0 + SX + DD + 1);
    } else {
        const int ox = (ix0 < HH - 1) ? SX : 0;
        const int oy = (iy0 < WW - 1) ? DD : 0;
        const int oz = (iz0 < DD - 1) ? 1  : 0;
        c000 = __ldg(p0);
        c001 = __ldg(p0 + oz);
        c010 = __ldg(p0 + oy);
        c011 = __ldg(p0 + oy + oz);
        c100 = __ldg(p0 + ox);
        c101 = __ldg(p0 + ox + oz);
        c110 = __ldg(p0 + ox + oy);
        c111 = __ldg(p0 + ox + oy + oz);
    }

    const float c00 = fmaf(tz, c001 - c000, c000);
    const float c01 = fmaf(tz, c011 - c010, c010);
    const float c10 = fmaf(tz, c101 - c100, c100);
    const float c11 = fmaf(tz, c111 - c110, c110);
    const float c0  = fmaf(ty, c01 - c00, c00);
    const float c1  = fmaf(ty, c11 - c10, c10);
    return fmaf(tx, c1 - c0, c0);
}

__global__ void __launch_bounds__(192)
affine_warp_kernel(const float* __restrict__ x,
                   const float* __restrict__ mats,
                   float* __restrict__ out)
{
    const int k = threadIdx.x;
    const int j = blockIdx.x;          // 0..47 ; voxels at j + q*48
    const int i = blockIdx.y;
    const int b = blockIdx.z;

    // broadcast this batch's 3x4 matrix through SMEM (kills the memcpy node)
    __shared__ float sM[12];
    if (threadIdx.x < 12) sM[threadIdx.x] = __ldg(mats + b * 12 + threadIdx.x);
    __syncthreads();

    const float fi = (float)i, fj = (float)j, fk = (float)k;
    const float lx0 = fmaf(sM[0], fi, fmaf(sM[1], fj, fmaf(sM[ 2], fk, sM[ 3])));
    const float ly0 = fmaf(sM[4], fi, fmaf(sM[5], fj, fmaf(sM[ 6], fk, sM[ 7])));
    const float lz0 = fmaf(sM[8], fi, fmaf(sM[9], fj, fmaf(sM[10], fk, sM[11])));

    const float dxj = sM[1] * (float)JQ;
    const float dyj = sM[5] * (float)JQ;
    const float dzj = sM[9] * (float)JQ;

    const float* __restrict__ vb = x + (size_t)b * (HH * WW * DD);

    const float v0 = sample_one(vb, lx0,         ly0,         lz0);
    const float v1 = sample_one(vb, lx0 + dxj,   ly0 + dyj,   lz0 + dzj);
    const float v2 = sample_one(vb, lx0 + 2*dxj, ly0 + 2*dyj, lz0 + 2*dzj);
    const float v3 = sample_one(vb, lx0 + 3*dxj, ly0 + 3*dyj, lz0 + 3*dzj);

    float* __restrict__ o = out + ((size_t)((b * HH + i) * WW + j) * DD + k);
    const size_t step = (size_t)JQ * DD;
    __stcs(o,            v0);
    __stcs(o + step,     v1);
    __stcs(o + 2 * step, v2);
    __stcs(o + 3 * step, v3);
}

extern "C" void kernel_launch(void* const* d_in, const int* in_sizes, int n_in,
                              void* d_out, int out_size)
{
    const float* x    = (const float*)d_in[0];
    const float* mats = (const float*)d_in[1];
    float* out        = (float*)d_out;

    dim3 grid(JQ, HH, BB);     // (j quarter, i, b)
    dim3 block(DD);            // k
    affine_warp_kernel<<<grid, block>>>(x, mats, out);
}